// round 12
// baseline (speedup 1.0000x reference)
#include <cuda_runtime.h>
#include <cuda_bf16.h>

#define BATCH     2048
#define NCLASSES  50257
#define KPOS      20
#define TPB       256
#define NGRP      64          // 64 groups x 32 rows

// Scratch (allocation-free requirement -> __device__ globals).
__device__ float        g_row_loss[BATCH];
__device__ unsigned int g_grp[NGRP];
__device__ unsigned int g_done = 0;

// acq_rel atomic add: release publishes this thread's prior stores (row loss)
// without a full MEMBAR.GPU flush; acquire chains visibility group->root->reader.
__device__ __forceinline__ unsigned int atom_add_acqrel(unsigned int* p, unsigned int v) {
    unsigned int old;
    asm volatile("atom.acq_rel.gpu.global.add.u32 %0, [%1], %2;"
                 : "=r"(old) : "l"(p), "r"(v) : "memory");
    return old;
}

__device__ __forceinline__ float softplus_f(float x) {
    // log(1+exp(x)) = max(x,0) + log(1+exp(-|x|)); exp arg <= 0 -> value in (0,1]
    return fmaxf(x, 0.0f) + __logf(1.0f + __expf(-fabsf(x)));
}

// Accumulate max(x,0) linearly; fold log terms into products (factor in (1,2]).
// One __logf per <=16 factors (prod <= 2^16, fp32-safe).
#define PROC4(v)                                                        \
    do {                                                                \
        lin += fmaxf((v).x, 0.0f) + fmaxf((v).y, 0.0f)                  \
             + fmaxf((v).z, 0.0f) + fmaxf((v).w, 0.0f);                 \
        p0 *= (1.0f + __expf(-fabsf((v).x)))                            \
            * (1.0f + __expf(-fabsf((v).y)));                           \
        p1 *= (1.0f + __expf(-fabsf((v).z)))                            \
            * (1.0f + __expf(-fabsf((v).w)));                           \
    } while (0)

__global__ __launch_bounds__(TPB)
void mlsm_row_kernel(const float* __restrict__ inp, const int* __restrict__ tgt,
                     float* __restrict__ out) {
    const int row = blockIdx.x;
    const int tid = threadIdx.x;
    const float* __restrict__ rp = inp + (size_t)row * NCLASSES;

    __shared__ int   s_t[KPOS];
    __shared__ float s_warp[TPB / 32];
    __shared__ float s_total;

    if (tid < KPOS) s_t[tid] = tgt[row * KPOS + tid];

    // Row base only 4B-aligned (NCLASSES odd): scalar prologue to 16B alignment.
    const int mis = (int)(((size_t)row * NCLASSES) & 3);
    const int pro = (4 - mis) & 3;

    float acc = 0.0f;
    if (tid < pro) acc += softplus_f(rp[tid]);

    const float4* __restrict__ vp = (const float4*)(rp + pro);
    const int nv = (NCLASSES - pro) >> 2;

    // Hot loop (R4-proven): 4 front-batched LDG.128 (MLP=4), default caching,
    // 16 elements per __logf.
    int i = tid;
    for (; i + 3 * TPB < nv; i += 4 * TPB) {
        float4 a = vp[i];
        float4 b = vp[i + TPB];
        float4 c = vp[i + 2 * TPB];
        float4 d = vp[i + 3 * TPB];
        float lin = 0.0f, p0 = 1.0f, p1 = 1.0f;
        PROC4(a); PROC4(b); PROC4(c); PROC4(d);
        acc += lin + __logf(p0 * p1);
    }
    for (; i < nv; i += TPB) {
        float4 a = vp[i];
        float lin = 0.0f, p0 = 1.0f, p1 = 1.0f;
        PROC4(a);
        acc += lin + __logf(p0 * p1);
    }
    const int base = pro + (nv << 2);
    for (int j = base + tid; j < NCLASSES; j += TPB)
        acc += softplus_f(rp[j]);

    // Block reduce -> s_total (sum of softplus over the row).
    const int lane = tid & 31;
    const int wid  = tid >> 5;
    #pragma unroll
    for (int o = 16; o > 0; o >>= 1)
        acc += __shfl_down_sync(0xFFFFFFFFu, acc, o);
    if (lane == 0) s_warp[wid] = acc;
    __syncthreads();

    // Warps 1..7 are done after this point and exit with no further barriers.
    if (wid != 0) return;

    {
        float v = (lane < TPB / 32) ? s_warp[lane] : 0.0f;
        #pragma unroll
        for (int o = 16; o > 0; o >>= 1)
            v += __shfl_down_sync(0xFFFFFFFFu, v, o);
        if (lane == 0) s_total = v;   // stays warp-local via smem broadcast below
    }
    __syncwarp();

    // Warp 0: K=20 label handling -> row loss.
    float pos = 0.0f, corr = 0.0f;
    int   nfirst = 0;
    if (lane < KPOS) {
        const int t = s_t[lane];
        const float x = __ldg(rp + t);
        pos = -softplus_f(-x);                 // log_sigmoid, per occurrence
        bool first = true;
        #pragma unroll
        for (int j = 0; j < KPOS; ++j)
            if (j < lane && s_t[j] == t) first = false;
        if (first) { corr = softplus_f(x); nfirst = 1; }  // dedup'd
    }
    #pragma unroll
    for (int o = 16; o > 0; o >>= 1) {
        pos    += __shfl_down_sync(0xFFFFFFFFu, pos, o);
        corr   += __shfl_down_sync(0xFFFFFFFFu, corr, o);
        nfirst += __shfl_down_sync(0xFFFFFFFFu, nfirst, o);
    }

    // Lane 0: publish row loss, then hierarchical arrival (low-contention).
    int last = 0;
    if (lane == 0) {
        const float neg_mean = (corr - s_total) / (float)(NCLASSES - nfirst);
        g_row_loss[row] = pos / (float)KPOS + neg_mean;
        const unsigned int g = (unsigned int)row >> 5;      // 32 rows per group
        if (atom_add_acqrel(&g_grp[g], 1u) == 31u)          // last in group
            if (atom_add_acqrel(&g_done, 1u) == NGRP - 1u)  // last group
                last = 1;
    }
    last = __shfl_sync(0xFFFFFFFFu, last, 0);

    // Final reduce (warp 0 of the very last CTA): fixed order -> deterministic.
    if (last) {
        float a = 0.0f;
        for (int r = lane; r < BATCH; r += 32)
            a += __ldcg(&g_row_loss[r]);
        #pragma unroll
        for (int o = 16; o > 0; o >>= 1)
            a += __shfl_down_sync(0xFFFFFFFFu, a, o);
        // Reset counters for the next graph replay.
        g_grp[lane]      = 0u;
        g_grp[lane + 32] = 0u;
        if (lane == 0) {
            out[0] = -a / (float)BATCH;
            g_done = 0u;
        }
    }
}

extern "C" void kernel_launch(void* const* d_in, const int* in_sizes, int n_in,
                              void* d_out, int out_size) {
    const float* inp = (const float*)d_in[0];
    const int*   tgt = (const int*)d_in[1];
    if (n_in >= 2 && in_sizes[0] == BATCH * KPOS && in_sizes[1] == BATCH * NCLASSES) {
        inp = (const float*)d_in[1];
        tgt = (const int*)d_in[0];
    }
    mlsm_row_kernel<<<BATCH, TPB>>>(inp, tgt, (float*)d_out);
}

// round 13
// speedup vs baseline: 1.0315x; 1.0315x over previous
#include <cuda_runtime.h>
#include <cuda_bf16.h>

#define BATCH     2048
#define NCLASSES  50257
#define KPOS      20
#define TPB       256

// Scratch (allocation-free requirement -> __device__ globals).
__device__ float        g_row_loss[BATCH];
__device__ unsigned int g_done = 0;

__device__ __forceinline__ float softplus_f(float x) {
    // log(1+exp(x)) = max(x,0) + log(1+exp(-|x|)); exp arg <= 0 -> value in (0,1]
    return fmaxf(x, 0.0f) + __logf(1.0f + __expf(-fabsf(x)));
}

// Accumulate max(x,0) linearly; fold log terms into products (factor in (1,2]).
// One __logf per 8 factors here (prod <= 2^8, fp32-safe with huge margin).
#define PROC4(v)                                                        \
    do {                                                                \
        lin += fmaxf((v).x, 0.0f) + fmaxf((v).y, 0.0f)                  \
             + fmaxf((v).z, 0.0f) + fmaxf((v).w, 0.0f);                 \
        p0 *= (1.0f + __expf(-fabsf((v).x)))                            \
            * (1.0f + __expf(-fabsf((v).y)));                           \
        p1 *= (1.0f + __expf(-fabsf((v).z)))                            \
            * (1.0f + __expf(-fabsf((v).w)));                           \
    } while (0)

__global__ __launch_bounds__(TPB)
void mlsm_row_kernel(const float* __restrict__ inp, const int* __restrict__ tgt,
                     float* __restrict__ out) {
    const int row = blockIdx.x;
    const int tid = threadIdx.x;
    const float* __restrict__ rp = inp + (size_t)row * NCLASSES;

    __shared__ int   s_t[KPOS];
    __shared__ float s_warp[TPB / 32];
    __shared__ float s_total;
    __shared__ int   s_last;

    if (tid < KPOS) s_t[tid] = tgt[row * KPOS + tid];

    // Row base only 4B-aligned (NCLASSES odd): scalar prologue to 16B alignment.
    const int mis = (int)(((size_t)row * NCLASSES) & 3);
    const int pro = (4 - mis) & 3;

    float acc = 0.0f;
    if (tid < pro) acc += softplus_f(rp[tid]);

    const float4* __restrict__ vp = (const float4*)(rp + pro);
    const int nv = (NCLASSES - pro) >> 2;

    // Hot loop: MLP_p1 = 2 (two front-batched LDG.128). Per the B300 spr_max
    // model, oe*MLP_p1 = 16 ~= Q_th keeps cross-CTA L1tex-queue spread at the
    // ~1.1 floor (vs ~1.3 at MLP_p1=4). 16KB/SM in flight still covers DRAM
    // latency with 2x margin. unroll 1 so ptxas cannot re-batch the loads.
    int i = tid;
    #pragma unroll 1
    for (; i + TPB < nv; i += 2 * TPB) {
        float4 a = __ldcs(vp + i);
        float4 b = __ldcs(vp + i + TPB);
        float lin = 0.0f, p0 = 1.0f, p1 = 1.0f;
        PROC4(a); PROC4(b);
        acc += lin + __logf(p0 * p1);
    }
    #pragma unroll 1
    for (; i < nv; i += TPB) {
        float4 a = __ldcs(vp + i);
        float lin = 0.0f, p0 = 1.0f, p1 = 1.0f;
        PROC4(a);
        acc += lin + __logf(p0 * p1);
    }
    const int base = pro + (nv << 2);
    for (int j = base + tid; j < NCLASSES; j += TPB)
        acc += softplus_f(rp[j]);

    // Block reduce -> s_total (sum of softplus over the row).
    const int lane = tid & 31;
    const int wid  = tid >> 5;
    #pragma unroll
    for (int o = 16; o > 0; o >>= 1)
        acc += __shfl_down_sync(0xFFFFFFFFu, acc, o);
    if (lane == 0) s_warp[wid] = acc;
    __syncthreads();
    if (wid == 0) {
        float v = (lane < TPB / 32) ? s_warp[lane] : 0.0f;
        #pragma unroll
        for (int o = 16; o > 0; o >>= 1)
            v += __shfl_down_sync(0xFFFFFFFFu, v, o);
        if (lane == 0) s_total = v;
    }
    __syncthreads();

    // Warp 0: K=20 label handling -> row loss.
    if (wid == 0) {
        float pos = 0.0f, corr = 0.0f;
        int   nfirst = 0;
        if (lane < KPOS) {
            const int t = s_t[lane];
            const float x = __ldg(rp + t);
            pos = -softplus_f(-x);                 // log_sigmoid, per occurrence
            bool first = true;
            #pragma unroll
            for (int j = 0; j < KPOS; ++j)
                if (j < lane && s_t[j] == t) first = false;
            if (first) { corr = softplus_f(x); nfirst = 1; }  // dedup'd
        }
        #pragma unroll
        for (int o = 16; o > 0; o >>= 1) {
            pos    += __shfl_down_sync(0xFFFFFFFFu, pos, o);
            corr   += __shfl_down_sync(0xFFFFFFFFu, corr, o);
            nfirst += __shfl_down_sync(0xFFFFFFFFu, nfirst, o);
        }
        if (lane == 0) {
            const float neg_mean = (corr - s_total) / (float)(NCLASSES - nfirst);
            g_row_loss[row] = pos / (float)KPOS + neg_mean;
        }
    }
    __syncthreads();   // order g_row_loss write before the fence below

    // Fused final reduce (R5-proven): last CTA sums all row losses (fixed
    // order -> deterministic) and resets the counter for the next replay.
    if (tid == 0) {
        __threadfence();
        unsigned int old = atomicAdd(&g_done, 1u);
        s_last = (old == BATCH - 1u) ? 1 : 0;
    }
    __syncthreads();
    if (s_last) {
        float a = 0.0f;
        for (int r = tid; r < BATCH; r += TPB)
            a += __ldcg(&g_row_loss[r]);           // bypass L1: cross-CTA data
        #pragma unroll
        for (int o = 16; o > 0; o >>= 1)
            a += __shfl_down_sync(0xFFFFFFFFu, a, o);
        if (lane == 0) s_warp[wid] = a;
        __syncthreads();
        if (wid == 0) {
            float v = (lane < TPB / 32) ? s_warp[lane] : 0.0f;
            #pragma unroll
            for (int o = 16; o > 0; o >>= 1)
                v += __shfl_down_sync(0xFFFFFFFFu, v, o);
            if (lane == 0) {
                out[0] = -v / (float)BATCH;
                g_done = 0;                        // reset for next replay
            }
        }
    }
}

extern "C" void kernel_launch(void* const* d_in, const int* in_sizes, int n_in,
                              void* d_out, int out_size) {
    const float* inp = (const float*)d_in[0];
    const int*   tgt = (const int*)d_in[1];
    if (n_in >= 2 && in_sizes[0] == BATCH * KPOS && in_sizes[1] == BATCH * NCLASSES) {
        inp = (const float*)d_in[1];
        tgt = (const int*)d_in[0];
    }
    mlsm_row_kernel<<<BATCH, TPB>>>(inp, tgt, (float*)d_out);
}

// round 14
// speedup vs baseline: 1.0746x; 1.0418x over previous
#include <cuda_runtime.h>
#include <cuda_bf16.h>

#define BATCH     2048
#define NCLASSES  50257
#define KPOS      20
#define TPB       256

// Scratch (allocation-free requirement -> __device__ global).
__device__ __align__(16) float g_row_loss[BATCH];

__device__ __forceinline__ float softplus_f(float x) {
    // log(1+exp(x)) = max(x,0) + log(1+exp(-|x|)); exp arg <= 0 -> value in (0,1]
    return fmaxf(x, 0.0f) + __logf(1.0f + __expf(-fabsf(x)));
}

// Accumulate max(x,0) linearly; fold log terms into products (factor in (1,2]).
// One __logf per <=16 factors (prod <= 2^16, fp32-safe).
#define PROC4(v)                                                        \
    do {                                                                \
        lin += fmaxf((v).x, 0.0f) + fmaxf((v).y, 0.0f)                  \
             + fmaxf((v).z, 0.0f) + fmaxf((v).w, 0.0f);                 \
        p0 *= (1.0f + __expf(-fabsf((v).x)))                            \
            * (1.0f + __expf(-fabsf((v).y)));                           \
        p1 *= (1.0f + __expf(-fabsf((v).z)))                            \
            * (1.0f + __expf(-fabsf((v).w)));                           \
    } while (0)

__global__ __launch_bounds__(TPB)
void mlsm_row_kernel(const float* __restrict__ inp, const int* __restrict__ tgt) {
    const int row = blockIdx.x;
    const int tid = threadIdx.x;
    const float* __restrict__ rp = inp + (size_t)row * NCLASSES;

    __shared__ int   s_t[KPOS];
    __shared__ float s_warp[TPB / 32];
    __shared__ float s_total;

    if (tid < KPOS) s_t[tid] = tgt[row * KPOS + tid];

    // Row base only 4B-aligned (NCLASSES odd): scalar prologue to 16B alignment.
    const int mis = (int)(((size_t)row * NCLASSES) & 3);
    const int pro = (4 - mis) & 3;

    float acc = 0.0f;
    if (tid < pro) acc += softplus_f(rp[tid]);

    const float4* __restrict__ vp = (const float4*)(rp + pro);
    const int nv = (NCLASSES - pro) >> 2;

    // R4-proven hot loop: 4 front-batched LDG.128 (MLP=4), default caching,
    // 16 elements per __logf. NO tail code, NO fences, NO atomics.
    int i = tid;
    for (; i + 3 * TPB < nv; i += 4 * TPB) {
        float4 a = vp[i];
        float4 b = vp[i + TPB];
        float4 c = vp[i + 2 * TPB];
        float4 d = vp[i + 3 * TPB];
        float lin = 0.0f, p0 = 1.0f, p1 = 1.0f;
        PROC4(a); PROC4(b); PROC4(c); PROC4(d);
        acc += lin + __logf(p0 * p1);
    }
    for (; i < nv; i += TPB) {
        float4 a = vp[i];
        float lin = 0.0f, p0 = 1.0f, p1 = 1.0f;
        PROC4(a);
        acc += lin + __logf(p0 * p1);
    }
    const int base = pro + (nv << 2);
    for (int j = base + tid; j < NCLASSES; j += TPB)
        acc += softplus_f(rp[j]);

    // Block reduce -> s_total (sum of softplus over the row).
    const int lane = tid & 31;
    const int wid  = tid >> 5;
    #pragma unroll
    for (int o = 16; o > 0; o >>= 1)
        acc += __shfl_down_sync(0xFFFFFFFFu, acc, o);
    if (lane == 0) s_warp[wid] = acc;
    __syncthreads();
    if (wid == 0) {
        float v = (lane < TPB / 32) ? s_warp[lane] : 0.0f;
        #pragma unroll
        for (int o = 16; o > 0; o >>= 1)
            v += __shfl_down_sync(0xFFFFFFFFu, v, o);
        if (lane == 0) s_total = v;
    }
    __syncthreads();

    // Warp 0: K=20 label handling -> row loss.
    if (wid == 0) {
        float pos = 0.0f, corr = 0.0f;
        int   nfirst = 0;
        if (lane < KPOS) {
            const int t = s_t[lane];
            const float x = __ldg(rp + t);
            pos = -softplus_f(-x);                 // log_sigmoid, per occurrence
            bool first = true;
            #pragma unroll
            for (int j = 0; j < KPOS; ++j)
                if (j < lane && s_t[j] == t) first = false;
            if (first) { corr = softplus_f(x); nfirst = 1; }  // dedup'd
        }
        #pragma unroll
        for (int o = 16; o > 0; o >>= 1) {
            pos    += __shfl_down_sync(0xFFFFFFFFu, pos, o);
            corr   += __shfl_down_sync(0xFFFFFFFFu, corr, o);
            nfirst += __shfl_down_sync(0xFFFFFFFFu, nfirst, o);
        }
        if (lane == 0) {
            const float neg_mean = (corr - s_total) / (float)(NCLASSES - nfirst);
            g_row_loss[row] = pos / (float)KPOS + neg_mean;
            // PDL: signal this CTA's contribution is published. The dependent
            // reduce kernel's griddepcontrol.wait releases once ALL CTAs have
            // signaled (or exited), with memory visibility guaranteed for
            // stores issued before the signal.
            asm volatile("griddepcontrol.launch_dependents;" ::: "memory");
        }
    }
}

__global__ __launch_bounds__(256)
void mlsm_reduce_kernel(float* __restrict__ out) {
    // Block until all primary CTAs have published their row losses.
    asm volatile("griddepcontrol.wait;" ::: "memory");

    const int tid  = threadIdx.x;
    const int lane = tid & 31;
    const int wid  = tid >> 5;
    __shared__ float s_warp[8];

    // 2048 floats = 512 float4; 256 threads x 2 vector loads. Fixed order ->
    // deterministic.
    const float4* __restrict__ v = (const float4*)g_row_loss;
    float4 x = v[tid];
    float4 y = v[tid + 256];
    float a = ((x.x + x.y) + (x.z + x.w)) + ((y.x + y.y) + (y.z + y.w));

    #pragma unroll
    for (int o = 16; o > 0; o >>= 1)
        a += __shfl_down_sync(0xFFFFFFFFu, a, o);
    if (lane == 0) s_warp[wid] = a;
    __syncthreads();
    if (wid == 0) {
        float t = (lane < 8) ? s_warp[lane] : 0.0f;
        #pragma unroll
        for (int o = 4; o > 0; o >>= 1)
            t += __shfl_down_sync(0xFFFFFFFFu, t, o);
        if (lane == 0)
            out[0] = -t / (float)BATCH;
    }
}

extern "C" void kernel_launch(void* const* d_in, const int* in_sizes, int n_in,
                              void* d_out, int out_size) {
    const float* inp = (const float*)d_in[0];
    const int*   tgt = (const int*)d_in[1];
    if (n_in >= 2 && in_sizes[0] == BATCH * KPOS && in_sizes[1] == BATCH * NCLASSES) {
        inp = (const float*)d_in[1];
        tgt = (const int*)d_in[0];
    }

    mlsm_row_kernel<<<BATCH, TPB>>>(inp, tgt);

    // Dependent launch: reduce kernel goes resident while the row kernel runs;
    // its griddepcontrol.wait releases as soon as all row CTAs signal.
    cudaLaunchConfig_t cfg = {};
    cfg.gridDim  = dim3(1, 1, 1);
    cfg.blockDim = dim3(256, 1, 1);
    cfg.dynamicSmemBytes = 0;
    cfg.stream = 0;   // legacy default stream (same one the harness captures)
    cudaLaunchAttribute attr[1];
    attr[0].id = cudaLaunchAttributeProgrammaticStreamSerialization;
    attr[0].val.programmaticStreamSerializationAllowed = 1;
    cfg.attrs = attr;
    cfg.numAttrs = 1;
    cudaLaunchKernelEx(&cfg, mlsm_reduce_kernel, (float*)d_out);
}